// round 15
// baseline (speedup 1.0000x reference)
#include <cuda_runtime.h>
#include <stdint.h>

// Shapes (fixed by the problem)
#define B    8
#define C    256
#define HIN  64          // input spatial 64x64
#define S    (HIN*HIN)   // 4096
#define HO   256         // output spatial 256x256
#define K    21
#define EPSF 1e-6f

#define SPLIT   16            // s-range splits (4 y-rows per block)
#define SRANGE  (S/SPLIT)     // 256 s per block
#define SCH     64            // s per feats smem chunk
#define NCH     (SRANGE/SCH)  // 4
#define FSTR    68            // padded row stride (floats): 272B (16B-aligned for cp16)
#define NCTA    (SPLIT*B)     // 128 CTAs <= 148 SMs: all co-resident at occ 1
#define NT      768           // 24 warps = 6 per SMSP

// smem layout (dynamic):
//   [0, 43008)       Ws : resident W dup-pairs [K][SRANGE] u64 (later: reduction)
//   [43008, 54432)   Cs : counts [4][K][68] u16 (own region, no aliasing)
//   [54528, 193792)  Fs : feats double buffer [2][C][FSTR] f32
#define WS_BYTES (K*SRANGE*8)                       // 43008
#define CS_OFF   WS_BYTES
#define CS_BYTES (4*K*68*2)                         // 11424
#define FS_OFF   ((CS_OFF + CS_BYTES + 127) & ~127) // 54528
#define FS_BYTES (C*FSTR*4)                         // 69632
#define SMEM_D   (FS_OFF + 2*FS_BYTES)              // 193792 -> occ 1 FORCED

// ---------------- scratch (__device__ globals; zero-init at load) -------------
__device__ unsigned g_rowcnt[B * K * HIN];        // exact 64*count per (b,k,y)
__device__ float    g_sums[SPLIT * B * K * C];    // partial per-class sums
__device__ unsigned g_ctr;                        // monotonic epoch counter

__device__ __forceinline__ int bil_w8(int Yx, int r) {
    int t  = 2 * Yx - 3;
    int y0 = ((t + 8) >> 3) - 1;
    int f8 = (t + 8) & 7;
    int y0c = min(max(y0, 0), HIN - 1);
    int y1c = min(max(y0 + 1, 0), HIN - 1);
    int w = 0;
    if (y0c == r) w += 8 - f8;
    if (y1c == r) w += f8;
    return w;
}

__device__ __forceinline__ void fma2(uint64_t& d, uint64_t a, uint64_t b) {
    asm("fma.rn.f32x2 %0, %1, %2, %0;" : "+l"(d) : "l"(a), "l"(b));
}
__device__ __forceinline__ uint64_t add2(uint64_t a, uint64_t b) {
    uint64_t d; asm("add.rn.f32x2 %0, %1, %2;" : "=l"(d) : "l"(a), "l"(b)); return d;
}
__device__ __forceinline__ uint64_t pack2(float x, float y) {
    uint64_t r; asm("mov.b64 %0, {%1, %2};" : "=l"(r) : "f"(x), "f"(y)); return r;
}
__device__ __forceinline__ void unpack2(float& x, float& y, uint64_t a) {
    asm("mov.b64 {%0, %1}, %2;" : "=f"(x), "=f"(y) : "l"(a));
}
__device__ __forceinline__ void cp16(void* dst, const void* src) {
    unsigned u = (unsigned)__cvta_generic_to_shared(dst);
    asm volatile("cp.async.cg.shared.global [%0], [%1], 16;" :: "r"(u), "l"(src));
}

// ---------------- THE kernel: masks -> W -> sums -> barrier -> prototypes ----
// grid (SPLIT, 1, B) = 128 CTAs, 768 threads (24 warps = 6/SMSP), occ 1 forced.
// threads 0-255: register mask-prologue; threads 256-767: cp.async prefetch of
// feats chunks 0 and 1 (each a per-thread commit group, in order).
// Mainloop: warp = (kt x cg x sub); kt owns 7 classes; lane owns channels
// {cg*128+lane, +32, +64, +96}; 2-s inner step keeps regs ~65 (85 budget).
extern "C" __global__ void __launch_bounds__(NT, 1) kernD(
        const float* __restrict__ feats, const int* __restrict__ masks,
        float* __restrict__ out) {
    extern __shared__ unsigned char smem[];
    uint64_t* Ws = (uint64_t*)smem;                 // [K][SRANGE]
    uint16_t* Cs = (uint16_t*)(smem + CS_OFF);      // [4][K][68]
    float*    Fs = (float*)(smem + FS_OFF);         // [2][C][FSTR]

    int split = blockIdx.x, b = blockIdx.z;
    int flat = b * SPLIT + split;                   // 0..127
    int tid = threadIdx.x, warp = tid >> 5, lane = tid & 31;
    int kt = warp >> 3, cg = (warp >> 2) & 1, sub = warp & 3;
    int k0 = kt * 7;

    const float* Fg = feats + (size_t)b * C * S;
    const int sbase0 = split * SRANGE;

    if (tid < 256) {
        // ---- Prologue: direct 8x8 mask window, all-register, exact ints ----
        int x = tid & 63, yy = tid >> 6;
        int y = split * 4 + yy;

        unsigned wy8[8], wx8[8];
        int po[4];
        #pragma unroll
        for (int d = 0; d < 8; d++) {
            int Y = 4 * y - 2 + d;
            wy8[d] = (Y < 0 || Y >= HO) ? 0u : (unsigned)bil_w8(Y, y);
            int X = 4 * x - 2 + d;
            wx8[d] = (X < 0 || X >= HO) ? 0u : (unsigned)bil_w8(X, x);
        }
        #pragma unroll
        for (int j = 0; j < 4; j++)
            po[j] = min(max(4 * x - 2 + 2 * j, 0), HO - 2) >> 1;

        unsigned acc12[12];
        #pragma unroll
        for (int j = 0; j < 12; j++) acc12[j] = 0u;

        #pragma unroll
        for (int dy = 0; dy < 8; dy++) {
            unsigned wy = wy8[dy];
            if (wy == 0) continue;                  // warp-uniform (boundary)
            int Y = 4 * y - 2 + dy;
            const int2* row = (const int2*)(masks + ((size_t)b * HO + Y) * HO);
            uint64_t r0 = 0, r1 = 0, r2 = 0;
            #pragma unroll
            for (int j = 0; j < 4; j++) {
                int2 p = row[po[j]];
                #pragma unroll
                for (int h = 0; h < 2; h++) {
                    int lbl = h ? p.y : p.x;
                    unsigned wx = wx8[2 * j + h];
                    uint64_t a = (uint64_t)wx << ((lbl & 7) * 8);
                    a = ((unsigned)lbl < (unsigned)K) ? a : 0ull;
                    int s3 = lbl >> 3;
                    r0 += (s3 == 0) ? a : 0ull;
                    r1 += (s3 == 1) ? a : 0ull;
                    r2 += (s3 == 2) ? a : 0ull;
                }
            }
            unsigned v0 = (unsigned)r0, v1 = (unsigned)(r0 >> 32);
            unsigned v2 = (unsigned)r1, v3 = (unsigned)(r1 >> 32);
            unsigned v4 = (unsigned)r2, v5 = (unsigned)(r2 >> 32);
            acc12[0]  += __byte_perm(v0, 0, 0x4140) * wy;
            acc12[1]  += __byte_perm(v0, 0, 0x4342) * wy;
            acc12[2]  += __byte_perm(v1, 0, 0x4140) * wy;
            acc12[3]  += __byte_perm(v1, 0, 0x4342) * wy;
            acc12[4]  += __byte_perm(v2, 0, 0x4140) * wy;
            acc12[5]  += __byte_perm(v2, 0, 0x4342) * wy;
            acc12[6]  += __byte_perm(v3, 0, 0x4140) * wy;
            acc12[7]  += __byte_perm(v3, 0, 0x4342) * wy;
            acc12[8]  += __byte_perm(v4, 0, 0x4140) * wy;
            acc12[9]  += __byte_perm(v4, 0, 0x4342) * wy;
            acc12[10] += __byte_perm(v5, 0, 0x4140) * wy;
            acc12[11] += __byte_perm(v5, 0, 0x4342) * wy;
        }

        int sl = yy * HIN + x;
        #pragma unroll
        for (int k = 0; k < K; k++) {
            unsigned val = (acc12[k >> 1] >> ((k & 1) * 16)) & 0xFFFFu;
            float f = (float)val * (1.0f / 64.0f);
            Ws[k * SRANGE + sl] = pack2(f, f);
            Cs[(yy * K + k) * 68 + x] = (uint16_t)val;
        }
    } else {
        // ---- Prefetch chunks 0 and 1 (512 threads; 2 per-thread groups) ----
        int t = tid - 256;
        for (int i = t; i < C * SCH / 4; i += 512) {
            int c = i >> 4, j4 = i & 15;
            cp16(&Fs[c * FSTR + j4 * 4], Fg + (size_t)c * S + sbase0 + j4 * 4);
        }
        asm volatile("cp.async.commit_group;");
        for (int i = t; i < C * SCH / 4; i += 512) {
            int c = i >> 4, j4 = i & 15;
            cp16(&Fs[C * FSTR + c * FSTR + j4 * 4],
                 Fg + (size_t)c * S + sbase0 + SCH + j4 * 4);
        }
        asm volatile("cp.async.commit_group;");
    }
    __syncthreads();   // Ws, Cs valid

    // exact integer row counts (one CTA per (split,b); no atomics)
    if (tid < 4 * K) {
        int yy = tid & 3, k = tid >> 2;
        const uint16_t* cp = &Cs[(yy * K + k) * 68];
        unsigned t = 0;
        #pragma unroll 16
        for (int xx = 0; xx < HIN; xx++) t += (unsigned)cp[xx];
        g_rowcnt[(b * K + k) * HIN + split * 4 + yy] = t;
    }

    uint64_t acc[14];   // [0..6]: (c,c+32) per j ; [7..13]: (c+64,c+96) per j
    #pragma unroll
    for (int j = 0; j < 14; j++) acc[j] = 0ull;

    #pragma unroll 1
    for (int chunk = 0; chunk < NCH; chunk++) {
        if (chunk == NCH - 1) asm volatile("cp.async.wait_group 0;");
        else                  asm volatile("cp.async.wait_group 1;");
        __syncthreads();

        const float* fbase = &Fs[(chunk & 1) * C * FSTR + (cg * 128 + lane) * FSTR];
        #pragma unroll
        for (int u = 0; u < 8; u++) {
            int sc = sub * 16 + u * 2;
            float2 f0 = *(const float2*)&fbase[sc];
            float2 f1 = *(const float2*)&fbase[32 * FSTR + sc];
            float2 f2 = *(const float2*)&fbase[64 * FSTR + sc];
            float2 f3 = *(const float2*)&fbase[96 * FSTR + sc];
            uint64_t pA0 = pack2(f0.x, f1.x), pB0 = pack2(f2.x, f3.x);
            uint64_t pA1 = pack2(f0.y, f1.y), pB1 = pack2(f2.y, f3.y);
            int sw = chunk * SCH + sc;
            #pragma unroll
            for (int j = 0; j < 7; j++) {
                ulonglong2 w = *(const ulonglong2*)&Ws[(k0 + j) * SRANGE + sw];  // broadcast
                fma2(acc[j],     pA0, w.x);  fma2(acc[j + 7], pB0, w.x);
                fma2(acc[j],     pA1, w.y);  fma2(acc[j + 7], pB1, w.y);
            }
        }
        __syncthreads();
        if (chunk + 2 < NCH) {
            int sb = sbase0 + (chunk + 2) * SCH;
            for (int i = tid; i < C * SCH / 4; i += NT) {
                int c = i >> 4, j4 = i & 15;
                cp16(&Fs[(chunk & 1) * C * FSTR + c * FSTR + j4 * 4],
                     Fg + (size_t)c * S + sb + j4 * 4);
            }
            asm volatile("cp.async.commit_group;");
        }
    }

    // ---- reduce 4 s-subrange warps per (kt,cg) group (Ws/Cs now dead) ----
    int gc = kt * 2 + cg;                          // 0..5
    uint64_t* red = (uint64_t*)smem;               // 12 x 14 x 32 u64 = 43008 B
    if (sub >= 2) {
        #pragma unroll
        for (int j = 0; j < 14; j++) red[((gc * 2 + (sub - 2)) * 14 + j) * 32 + lane] = acc[j];
    }
    __syncthreads();
    if (sub < 2) {
        #pragma unroll
        for (int j = 0; j < 14; j++) acc[j] = add2(acc[j], red[((gc * 2 + sub) * 14 + j) * 32 + lane]);
    }
    __syncthreads();
    if (sub == 1) {
        #pragma unroll
        for (int j = 0; j < 14; j++) red[(gc * 14 + j) * 32 + lane] = acc[j];
    }
    __syncthreads();
    if (sub == 0) {
        float* outp = &g_sums[(((size_t)split * B + b) * K) * C];
        int cbase = cg * 128 + lane;
        #pragma unroll
        for (int j = 0; j < 7; j++) {
            int k = k0 + j;
            uint64_t tA = add2(acc[j],     red[(gc * 14 + j) * 32 + lane]);
            uint64_t tB = add2(acc[j + 7], red[(gc * 14 + j + 7) * 32 + lane]);
            float a0, a1, a2, a3;
            unpack2(a0, a1, tA);
            unpack2(a2, a3, tB);
            outp[k * C + cbase]      = a0;
            outp[k * C + cbase + 32] = a1;
            outp[k * C + cbase + 64] = a2;
            outp[k * C + cbase + 96] = a3;
        }
    }

    // ---- grid barrier: 128 CTAs all co-resident (occ-1 forced) -> safe ----
    __shared__ unsigned s_my;
    __threadfence();
    __syncthreads();                               // all g_sums/rowcnt fenced
    if (tid == 0) s_my = atomicAdd(&g_ctr, 1u);
    __syncthreads();
    unsigned target = (s_my / (unsigned)NCTA + 1u) * (unsigned)NCTA;
    if (tid == 0) {
        while (atomicAdd(&g_ctr, 0u) < target) __nanosleep(128);
    }
    __syncthreads();

    // ---- fused finalization: 168 virtual blocks over 128 CTAs --------------
    __shared__ float redf[B][32];
    for (int vb = flat; vb < K * 8; vb += NCTA) {
        if (tid < 256) {
            int k = vb >> 3, cg8 = vb & 7;
            int eb = tid >> 5;                     // b
            int c = cg8 * 32 + lane;
            float v = 0.f;
            #pragma unroll
            for (int sp = 0; sp < SPLIT; sp++)
                v += __ldcg(&g_sums[((sp * B + eb) * K + k) * C + c]);
            const unsigned* rc = &g_rowcnt[(eb * K + k) * HIN];
            unsigned cr = __ldcg(&rc[lane]) + __ldcg(&rc[lane + 32]);
            #pragma unroll
            for (int o = 16; o > 0; o >>= 1) cr += __shfl_xor_sync(0xFFFFFFFFu, cr, o);
            v *= 1.0f / ((float)cr * (1.0f / 64.0f) + EPSF);
            redf[eb][lane] = v;
        }
        __syncthreads();
        if (tid < 32) {
            int k = vb >> 3, cg8 = vb & 7;
            float a = redf[0][lane];
            #pragma unroll
            for (int w = 1; w < B; w++) a += redf[w][lane];
            out[k * C + cg8 * 32 + lane] = a * (1.0f / (float)B);
        }
        __syncthreads();
    }
}

// ---------------- launch -----------------------------------------------------
extern "C" void kernel_launch(void* const* d_in, const int* in_sizes, int n_in,
                              void* d_out, int out_size) {
    const float* feats = (const float*)d_in[0];   // [8,256,64,64]
    const int*   masks = (const int*)d_in[1];     // [8,256,256]
    float*       out   = (float*)d_out;           // [21,256]

    cudaFuncSetAttribute(kernD, cudaFuncAttributeMaxDynamicSharedMemorySize, SMEM_D);

    kernD<<<dim3(SPLIT, 1, B), NT, SMEM_D>>>(feats, masks, out);
}

// round 16
// speedup vs baseline: 1.2257x; 1.2257x over previous
#include <cuda_runtime.h>
#include <stdint.h>

// Shapes (fixed by the problem)
#define B    8
#define C    256
#define HIN  64          // input spatial 64x64
#define S    (HIN*HIN)   // 4096
#define HO   256         // output spatial 256x256
#define K    21
#define EPSF 1e-6f

#define SPLIT   16            // s-range splits (4 y-rows per block)
#define SRANGE  (S/SPLIT)     // 256 s per block
#define SCH     64            // s per feats smem chunk
#define NCH     (SRANGE/SCH)  // 4
#define FSTR    65            // row stride (floats): 65 mod 32 == 1 -> CONFLICT-FREE
#define NCTA    (SPLIT*B)     // 128 CTAs <= 148 SMs: all co-resident at occ 1
#define NT      768           // 24 warps = 6 per SMSP

// smem layout (dynamic):
//   [0, 43008)       Ws : resident W dup-pairs [K][SRANGE] u64 (later: reduction)
//   [43008, 54432)   Cs : counts [4][K][68] u16
//   [54528, 187648)  Fs : feats double buffer [2][C][FSTR] f32
#define WS_BYTES (K*SRANGE*8)                       // 43008
#define CS_OFF   WS_BYTES
#define CS_BYTES (4*K*68*2)                         // 11424
#define FS_OFF   ((CS_OFF + CS_BYTES + 127) & ~127) // 54528
#define FS_BYTES (C*FSTR*4)                         // 66560
#define SMEM_D   (FS_OFF + 2*FS_BYTES)              // 187648 -> occ 1 forced

// ---------------- scratch (__device__ globals; zero-init at load) -------------
__device__ unsigned g_rowcnt[B * K * HIN];        // exact 64*count per (b,k,y)
__device__ float    g_sums[SPLIT * B * K * C];    // partial per-class sums
__device__ unsigned g_ctr;                        // monotonic epoch counter

__device__ __forceinline__ int bil_w8(int Yx, int r) {
    int t  = 2 * Yx - 3;
    int y0 = ((t + 8) >> 3) - 1;
    int f8 = (t + 8) & 7;
    int y0c = min(max(y0, 0), HIN - 1);
    int y1c = min(max(y0 + 1, 0), HIN - 1);
    int w = 0;
    if (y0c == r) w += 8 - f8;
    if (y1c == r) w += f8;
    return w;
}

__device__ __forceinline__ void fma2(uint64_t& d, uint64_t a, uint64_t b) {
    asm("fma.rn.f32x2 %0, %1, %2, %0;" : "+l"(d) : "l"(a), "l"(b));
}
__device__ __forceinline__ uint64_t add2(uint64_t a, uint64_t b) {
    uint64_t d; asm("add.rn.f32x2 %0, %1, %2;" : "=l"(d) : "l"(a), "l"(b)); return d;
}
__device__ __forceinline__ uint64_t pack2(float x, float y) {
    uint64_t r; asm("mov.b64 %0, {%1, %2};" : "=l"(r) : "f"(x), "f"(y)); return r;
}
__device__ __forceinline__ void unpack2(float& x, float& y, uint64_t a) {
    asm("mov.b64 {%0, %1}, %2;" : "=f"(x), "=f"(y) : "l"(a));
}
// 4-byte cp.async: gmem coalesced, smem bank = (c + j) mod 32 -> conflict-free
__device__ __forceinline__ void cp4(void* dst, const void* src) {
    unsigned u = (unsigned)__cvta_generic_to_shared(dst);
    asm volatile("cp.async.ca.shared.global [%0], [%1], 4;" :: "r"(u), "l"(src));
}

// ---------------- THE kernel: masks -> W -> sums -> barrier -> prototypes ----
// grid (SPLIT, 1, B) = 128 CTAs, 768 threads, occ 1 forced.
// threads 0-255: register mask-prologue; 256-767: cp.async prefetch chunks 0+1.
// Mainloop: warp = (kt x cg x sub); kt owns 7 classes; lane owns channels
// {cg*128+lane, +32, +64, +96}; ALL feats LDS conflict-free (FSTR=65).
extern "C" __global__ void __launch_bounds__(NT, 1) kernD(
        const float* __restrict__ feats, const int* __restrict__ masks,
        float* __restrict__ out) {
    extern __shared__ unsigned char smem[];
    uint64_t* Ws = (uint64_t*)smem;                 // [K][SRANGE]
    uint16_t* Cs = (uint16_t*)(smem + CS_OFF);      // [4][K][68]
    float*    Fs = (float*)(smem + FS_OFF);         // [2][C][FSTR]

    int split = blockIdx.x, b = blockIdx.z;
    int flat = b * SPLIT + split;                   // 0..127
    int tid = threadIdx.x, warp = tid >> 5, lane = tid & 31;
    int kt = warp >> 3, cg = (warp >> 2) & 1, sub = warp & 3;
    int k0 = kt * 7;

    const float* Fg = feats + (size_t)b * C * S;
    const int sbase0 = split * SRANGE;

    if (tid < 256) {
        // ---- Prologue: direct 8x8 mask window, all-register, exact ints ----
        int x = tid & 63, yy = tid >> 6;
        int y = split * 4 + yy;

        unsigned wy8[8], wx8[8];
        int po[4];
        #pragma unroll
        for (int d = 0; d < 8; d++) {
            int Y = 4 * y - 2 + d;
            wy8[d] = (Y < 0 || Y >= HO) ? 0u : (unsigned)bil_w8(Y, y);
            int X = 4 * x - 2 + d;
            wx8[d] = (X < 0 || X >= HO) ? 0u : (unsigned)bil_w8(X, x);
        }
        #pragma unroll
        for (int j = 0; j < 4; j++)
            po[j] = min(max(4 * x - 2 + 2 * j, 0), HO - 2) >> 1;

        unsigned acc12[12];
        #pragma unroll
        for (int j = 0; j < 12; j++) acc12[j] = 0u;

        #pragma unroll
        for (int dy = 0; dy < 8; dy++) {
            unsigned wy = wy8[dy];
            if (wy == 0) continue;                  // warp-uniform (boundary)
            int Y = 4 * y - 2 + dy;
            const int2* row = (const int2*)(masks + ((size_t)b * HO + Y) * HO);
            uint64_t r0 = 0, r1 = 0, r2 = 0;
            #pragma unroll
            for (int j = 0; j < 4; j++) {
                int2 p = row[po[j]];
                #pragma unroll
                for (int h = 0; h < 2; h++) {
                    int lbl = h ? p.y : p.x;
                    unsigned wx = wx8[2 * j + h];
                    uint64_t a = (uint64_t)wx << ((lbl & 7) * 8);
                    a = ((unsigned)lbl < (unsigned)K) ? a : 0ull;
                    int s3 = lbl >> 3;
                    r0 += (s3 == 0) ? a : 0ull;
                    r1 += (s3 == 1) ? a : 0ull;
                    r2 += (s3 == 2) ? a : 0ull;
                }
            }
            unsigned v0 = (unsigned)r0, v1 = (unsigned)(r0 >> 32);
            unsigned v2 = (unsigned)r1, v3 = (unsigned)(r1 >> 32);
            unsigned v4 = (unsigned)r2, v5 = (unsigned)(r2 >> 32);
            acc12[0]  += __byte_perm(v0, 0, 0x4140) * wy;
            acc12[1]  += __byte_perm(v0, 0, 0x4342) * wy;
            acc12[2]  += __byte_perm(v1, 0, 0x4140) * wy;
            acc12[3]  += __byte_perm(v1, 0, 0x4342) * wy;
            acc12[4]  += __byte_perm(v2, 0, 0x4140) * wy;
            acc12[5]  += __byte_perm(v2, 0, 0x4342) * wy;
            acc12[6]  += __byte_perm(v3, 0, 0x4140) * wy;
            acc12[7]  += __byte_perm(v3, 0, 0x4342) * wy;
            acc12[8]  += __byte_perm(v4, 0, 0x4140) * wy;
            acc12[9]  += __byte_perm(v4, 0, 0x4342) * wy;
            acc12[10] += __byte_perm(v5, 0, 0x4140) * wy;
            acc12[11] += __byte_perm(v5, 0, 0x4342) * wy;
        }

        int sl = yy * HIN + x;
        #pragma unroll
        for (int k = 0; k < K; k++) {
            unsigned val = (acc12[k >> 1] >> ((k & 1) * 16)) & 0xFFFFu;
            float f = (float)val * (1.0f / 64.0f);
            Ws[k * SRANGE + sl] = pack2(f, f);
            Cs[(yy * K + k) * 68 + x] = (uint16_t)val;
        }
    } else {
        // ---- Prefetch chunks 0 and 1 (512 threads; per-thread groups) ----
        int t = tid - 256;
        for (int i = t; i < C * SCH; i += 512) {
            int c = i >> 6, j = i & 63;
            cp4(&Fs[c * FSTR + j], Fg + (size_t)c * S + sbase0 + j);
        }
        asm volatile("cp.async.commit_group;");
        for (int i = t; i < C * SCH; i += 512) {
            int c = i >> 6, j = i & 63;
            cp4(&Fs[C * FSTR + c * FSTR + j], Fg + (size_t)c * S + sbase0 + SCH + j);
        }
        asm volatile("cp.async.commit_group;");
    }
    __syncthreads();   // Ws, Cs valid

    // exact integer row counts (one CTA per (split,b); no atomics)
    if (tid < 4 * K) {
        int yy = tid & 3, k = tid >> 2;
        const uint16_t* cp = &Cs[(yy * K + k) * 68];
        unsigned t = 0;
        #pragma unroll 16
        for (int xx = 0; xx < HIN; xx++) t += (unsigned)cp[xx];
        g_rowcnt[(b * K + k) * HIN + split * 4 + yy] = t;
    }

    uint64_t acc[14];   // [0..6]: (c,c+32) per j ; [7..13]: (c+64,c+96) per j
    #pragma unroll
    for (int j = 0; j < 14; j++) acc[j] = 0ull;

    #pragma unroll 1
    for (int chunk = 0; chunk < NCH; chunk++) {
        if (chunk == NCH - 1) asm volatile("cp.async.wait_group 0;");
        else                  asm volatile("cp.async.wait_group 1;");
        __syncthreads();

        const float* fbase = &Fs[(chunk & 1) * C * FSTR + (cg * 128 + lane) * FSTR];
        #pragma unroll
        for (int u = 0; u < 4; u++) {
            int sc = sub * 16 + u * 4;
            // 16 conflict-free scalar LDS.32 (lane stride 65 words == bank+1)
            float a0 = fbase[sc],            a1 = fbase[sc + 1];
            float a2 = fbase[sc + 2],        a3 = fbase[sc + 3];
            const float* f1 = fbase + 32 * FSTR;
            float b0 = f1[sc], b1 = f1[sc + 1], b2 = f1[sc + 2], b3 = f1[sc + 3];
            const float* f2 = fbase + 64 * FSTR;
            float c0 = f2[sc], c1 = f2[sc + 1], c2 = f2[sc + 2], c3 = f2[sc + 3];
            const float* f3 = fbase + 96 * FSTR;
            float d0 = f3[sc], d1 = f3[sc + 1], d2 = f3[sc + 2], d3 = f3[sc + 3];
            uint64_t pA0 = pack2(a0, b0), pB0 = pack2(c0, d0);
            uint64_t pA1 = pack2(a1, b1), pB1 = pack2(c1, d1);
            uint64_t pA2 = pack2(a2, b2), pB2 = pack2(c2, d2);
            uint64_t pA3 = pack2(a3, b3), pB3 = pack2(c3, d3);
            int sw = chunk * SCH + sc;
            #pragma unroll
            for (int j = 0; j < 7; j++) {
                const uint64_t* wr = &Ws[(k0 + j) * SRANGE + sw];
                ulonglong2 w01 = *(const ulonglong2*)wr;          // broadcast
                ulonglong2 w23 = *(const ulonglong2*)(wr + 2);    // broadcast
                fma2(acc[j],     pA0, w01.x);  fma2(acc[j + 7], pB0, w01.x);
                fma2(acc[j],     pA1, w01.y);  fma2(acc[j + 7], pB1, w01.y);
                fma2(acc[j],     pA2, w23.x);  fma2(acc[j + 7], pB2, w23.x);
                fma2(acc[j],     pA3, w23.y);  fma2(acc[j + 7], pB3, w23.y);
            }
        }
        __syncthreads();
        if (chunk + 2 < NCH) {
            int sb = sbase0 + (chunk + 2) * SCH;
            for (int i = tid; i < C * SCH; i += NT) {
                int c = i >> 6, j = i & 63;
                cp4(&Fs[(chunk & 1) * C * FSTR + c * FSTR + j],
                    Fg + (size_t)c * S + sb + j);
            }
            asm volatile("cp.async.commit_group;");
        }
    }

    // ---- reduce 4 s-subrange warps per (kt,cg) group (Ws/Cs now dead) ----
    int gc = kt * 2 + cg;                          // 0..5
    uint64_t* red = (uint64_t*)smem;               // 12 x 14 x 32 u64 = 43008 B
    if (sub >= 2) {
        #pragma unroll
        for (int j = 0; j < 14; j++) red[((gc * 2 + (sub - 2)) * 14 + j) * 32 + lane] = acc[j];
    }
    __syncthreads();
    if (sub < 2) {
        #pragma unroll
        for (int j = 0; j < 14; j++) acc[j] = add2(acc[j], red[((gc * 2 + sub) * 14 + j) * 32 + lane]);
    }
    __syncthreads();
    if (sub == 1) {
        #pragma unroll
        for (int j = 0; j < 14; j++) red[(gc * 14 + j) * 32 + lane] = acc[j];
    }
    __syncthreads();
    if (sub == 0) {
        float* outp = &g_sums[(((size_t)split * B + b) * K) * C];
        int cbase = cg * 128 + lane;
        #pragma unroll
        for (int j = 0; j < 7; j++) {
            int k = k0 + j;
            uint64_t tA = add2(acc[j],     red[(gc * 14 + j) * 32 + lane]);
            uint64_t tB = add2(acc[j + 7], red[(gc * 14 + j + 7) * 32 + lane]);
            float a0, a1, a2, a3;
            unpack2(a0, a1, tA);
            unpack2(a2, a3, tB);
            outp[k * C + cbase]      = a0;
            outp[k * C + cbase + 32] = a1;
            outp[k * C + cbase + 64] = a2;
            outp[k * C + cbase + 96] = a3;
        }
    }

    // ---- grid barrier: 128 CTAs all co-resident (occ-1 forced) -> safe ----
    __shared__ unsigned s_my;
    __threadfence();
    __syncthreads();                               // all g_sums/rowcnt fenced
    if (tid == 0) s_my = atomicAdd(&g_ctr, 1u);
    __syncthreads();
    unsigned target = (s_my / (unsigned)NCTA + 1u) * (unsigned)NCTA;
    if (tid == 0) {
        while (atomicAdd(&g_ctr, 0u) < target) __nanosleep(128);
    }
    __syncthreads();

    // ---- fused finalization: 168 virtual blocks over 128 CTAs --------------
    __shared__ float redf[B][32];
    for (int vb = flat; vb < K * 8; vb += NCTA) {
        if (tid < 256) {
            int k = vb >> 3, cg8 = vb & 7;
            int eb = tid >> 5;                     // b
            int c = cg8 * 32 + lane;
            float v = 0.f;
            #pragma unroll
            for (int sp = 0; sp < SPLIT; sp++)
                v += __ldcg(&g_sums[((sp * B + eb) * K + k) * C + c]);
            const unsigned* rc = &g_rowcnt[(eb * K + k) * HIN];
            unsigned cr = __ldcg(&rc[lane]) + __ldcg(&rc[lane + 32]);
            #pragma unroll
            for (int o = 16; o > 0; o >>= 1) cr += __shfl_xor_sync(0xFFFFFFFFu, cr, o);
            v *= 1.0f / ((float)cr * (1.0f / 64.0f) + EPSF);
            redf[eb][lane] = v;
        }
        __syncthreads();
        if (tid < 32) {
            int k = vb >> 3, cg8 = vb & 7;
            float a = redf[0][lane];
            #pragma unroll
            for (int w = 1; w < B; w++) a += redf[w][lane];
            out[k * C + cg8 * 32 + lane] = a * (1.0f / (float)B);
        }
        __syncthreads();
    }
}

// ---------------- launch -----------------------------------------------------
extern "C" void kernel_launch(void* const* d_in, const int* in_sizes, int n_in,
                              void* d_out, int out_size) {
    const float* feats = (const float*)d_in[0];   // [8,256,64,64]
    const int*   masks = (const int*)d_in[1];     // [8,256,256]
    float*       out   = (float*)d_out;           // [21,256]

    cudaFuncSetAttribute(kernD, cudaFuncAttributeMaxDynamicSharedMemorySize, SMEM_D);

    kernD<<<dim3(SPLIT, 1, B), NT, SMEM_D>>>(feats, masks, out);
}